// round 1
// baseline (speedup 1.0000x reference)
#include <cuda_runtime.h>

// Problem constants
// B=128, U=64, A=64, FIN=1, FPHI=FGAM=32, PHI_OUT=GAM_OUT=64
// Intermediate layout: [b][a][c][u]  (so per-(b,a) slices are contiguous 64x64)

#define NBA 8192            // B*A
#define SLICE 4096          // 64 channels * 64 u

// ---------------- scratch (device globals: allocation-free) ----------------
__device__ float g_cgT[128 * 64 * 64];                  // [b][a][u]
__device__ float g_msgs[(size_t)128 * 64 * 64 * 64];    // [b][a][c][u]
__device__ float g_r[(size_t)128 * 64 * 64 * 64];       // [b][a][c][u]
__device__ float g_sumsP[4 * 128 * 64 * 64];            // [q][b][c][u] partial a-sums
__device__ float g_wt[90560];                           // transposed weights Wt[c][o]

// transposed-weight offsets (floats)
#define OFF_PHI1_W1T 0
#define OFF_PHI1_W2T 128
#define OFF_PHIK_W1T 4224
#define OFF_PHIK_W2T 20864
#define OFF_G1_W1T   37248
#define OFF_G1_W2T   41408
#define OFF_GK_W1T   45504
#define OFF_GK_W2T   70080
#define OFF_G5_W1T   82368

// ---------------- prep: transpose all weight matrices to Wt[c][o] ----------
__global__ void prep_kernel(const float* __restrict__ phi1W1, const float* __restrict__ phi1W2,
                            const float* __restrict__ phiKW1, const float* __restrict__ phiKW2,
                            const float* __restrict__ g1W1,   const float* __restrict__ g1W2,
                            const float* __restrict__ gKW1,   const float* __restrict__ gKW2,
                            const float* __restrict__ g5W1) {
    const int id = blockIdx.x;
    const float* src;
    float* dst;
    int C;
    if (id == 0)       { src = phi1W1;                 dst = g_wt + OFF_PHI1_W1T;              C = 2;   }
    else if (id == 1)  { src = phi1W2;                 dst = g_wt + OFF_PHI1_W2T;              C = 64;  }
    else if (id < 6)   { int i = id - 2;  src = phiKW1 + i * 4160; dst = g_wt + OFF_PHIK_W1T + i * 4160; C = 65;  }
    else if (id < 10)  { int i = id - 6;  src = phiKW2 + i * 4096; dst = g_wt + OFF_PHIK_W2T + i * 4096; C = 64;  }
    else if (id == 10) { src = g1W1;                   dst = g_wt + OFF_G1_W1T;                C = 65;  }
    else if (id == 11) { src = g1W2;                   dst = g_wt + OFF_G1_W2T;                C = 64;  }
    else if (id < 15)  { int i = id - 12; src = gKW1 + i * 8192;  dst = g_wt + OFF_GK_W1T + i * 8192;   C = 128; }
    else if (id < 18)  { int i = id - 15; src = gKW2 + i * 4096;  dst = g_wt + OFF_GK_W2T + i * 4096;   C = 64;  }
    else               { src = g5W1;                   dst = g_wt + OFF_G5_W1T;                C = 128; }
    const int n = 64 * C;
    for (int j = threadIdx.x; j < n; j += blockDim.x) {
        int c = j >> 6, o = j & 63;       // dst layout [c][64]
        dst[j] = src[o * C + c];
    }
}

// ---------------- cg transpose: (B,U,A) -> (B,A,U) --------------------------
__global__ void cgt_kernel(const float* __restrict__ cg) {
    const int b = blockIdx.x;
    for (int j = threadIdx.x; j < 4096; j += 256) {
        int a = j >> 6, u = j & 63;
        g_cgT[b * 4096 + j] = cg[b * 4096 + u * 64 + a];
    }
}

// ---------------- partial sum over a-axis of msgs ---------------------------
__global__ void asum_kernel() {
    const int b = blockIdx.x >> 2, q = blockIdx.x & 3;
    const int t = threadIdx.x;   // 256 threads
    float4 acc[4];
#pragma unroll
    for (int k = 0; k < 4; ++k) acc[k] = make_float4(0.f, 0.f, 0.f, 0.f);
    const float4* base = reinterpret_cast<const float4*>(g_msgs + (size_t)b * 262144 + (size_t)q * 16 * 4096);
    for (int a = 0; a < 16; ++a) {
        const float4* p = base + a * 1024;
#pragma unroll
        for (int k = 0; k < 4; ++k) {
            float4 v = p[t + k * 256];
            acc[k].x += v.x; acc[k].y += v.y; acc[k].z += v.z; acc[k].w += v.w;
        }
    }
    float4* s4 = reinterpret_cast<float4*>(g_sumsP + (size_t)q * 524288 + b * 4096);
#pragma unroll
    for (int k = 0; k < 4; ++k) s4[t + k * 256] = acc[k];
}

// ---------------- GEMM helpers ----------------------------------------------
template<int CIN>
__device__ __forceinline__ void gemm_core(const float* __restrict__ sW, const float* __restrict__ sX,
                                          float acc[4][8], int to, int tu) {
#pragma unroll 4
    for (int c = 0; c < CIN; ++c) {
        float4 w  = *reinterpret_cast<const float4*>(sW + c * 64 + to);
        float4 x0 = *reinterpret_cast<const float4*>(sX + c * 64 + tu);
        float4 x1 = *reinterpret_cast<const float4*>(sX + c * 64 + tu + 4);
        float wv[4] = {w.x, w.y, w.z, w.w};
        float xv[8] = {x0.x, x0.y, x0.z, x0.w, x1.x, x1.y, x1.z, x1.w};
#pragma unroll
        for (int i = 0; i < 4; ++i)
#pragma unroll
            for (int j = 0; j < 8; ++j)
                acc[i][j] = fmaf(wv[i], xv[j], acc[i][j]);
    }
}

// column sums over u for channel rows 32..63 (needed by post_users)
__device__ __forceinline__ void colsum_top(const float* __restrict__ sH, float* __restrict__ sS, int t) {
    const int w = t >> 5, l = t & 31;
#pragma unroll
    for (int k = 0; k < 8; ++k) {
        const int o = 32 + w * 8 + k;
        float v = sH[o * 64 + l] + sH[o * 64 + 32 + l];
        v += __shfl_down_sync(0xffffffffu, v, 16);
        v += __shfl_down_sync(0xffffffffu, v, 8);
        v += __shfl_down_sync(0xffffffffu, v, 4);
        v += __shfl_down_sync(0xffffffffu, v, 2);
        v += __shfl_down_sync(0xffffffffu, v, 1);
        if (l == 0) sS[o] = v;
    }
}

// in-place post_users transform on sH rows 32..63: x <- (S - x)/63
__device__ __forceinline__ void post_top(float* __restrict__ sH, const float* __restrict__ sS, int t) {
    const float inv = 1.0f / 63.0f;
    float4* H4 = reinterpret_cast<float4*>(sH);
#pragma unroll
    for (int k = 0; k < 4; ++k) {
        int idx = t + k * 128;                 // 0..511 float4 within rows 32..63
        float s = sS[32 + (idx >> 4)];
        float4 v = H4[512 + idx];
        v.x = (s - v.x) * inv; v.y = (s - v.y) * inv;
        v.z = (s - v.z) * inv; v.w = (s - v.w) * inv;
        H4[512 + idx] = v;
    }
}

__device__ __forceinline__ void store_sH(const float acc[4][8], float* __restrict__ sH, int to, int tu) {
#pragma unroll
    for (int i = 0; i < 4; ++i) {
        *reinterpret_cast<float4*>(sH + (to + i) * 64 + tu)     = make_float4(acc[i][0], acc[i][1], acc[i][2], acc[i][3]);
        *reinterpret_cast<float4*>(sH + (to + i) * 64 + tu + 4) = make_float4(acc[i][4], acc[i][5], acc[i][6], acc[i][7]);
    }
}

// write with post_users transform applied (rows<32 raw, rows>=32: (S-x)/63)
__device__ __forceinline__ void write_post(const float acc[4][8], const float* __restrict__ sS,
                                           float* __restrict__ gout, int to, int tu) {
    const float inv = 1.0f / 63.0f;
#pragma unroll
    for (int i = 0; i < 4; ++i) {
        const int o = to + i;
        float v[8];
        if (o < 32) {
#pragma unroll
            for (int j = 0; j < 8; ++j) v[j] = acc[i][j];
        } else {
            const float s = sS[o];
#pragma unroll
            for (int j = 0; j < 8; ++j) v[j] = (s - acc[i][j]) * inv;
        }
        *reinterpret_cast<float4*>(gout + o * 64 + tu)     = make_float4(v[0], v[1], v[2], v[3]);
        *reinterpret_cast<float4*>(gout + o * 64 + tu + 4) = make_float4(v[4], v[5], v[6], v[7]);
    }
}

// ---------------- phi kernel ------------------------------------------------
// CIN=2: input = [cg; cg].   CIN=65: input = [cg; r].
template<int CIN>
__global__ void __launch_bounds__(128) phi_kernel(const float* __restrict__ b1,
                                                  const float* __restrict__ b2,
                                                  int w1off, int w2off) {
    extern __shared__ float smem[];
    constexpr int WROWS = (CIN > 64) ? CIN : 64;
    float* sX = smem;                  // CIN*64
    float* sW = sX + CIN * 64;         // WROWS*64
    float* sH = sW + WROWS * 64;       // 4096
    float* sS = sH + 4096;             // 64
    const int t = threadIdx.x;
    const int ba = blockIdx.x;

    if (CIN == 2) {
        if (t < 64) { float v = g_cgT[ba * 64 + t]; sX[t] = v; sX[64 + t] = v; }
    } else {
        if (t < 16) reinterpret_cast<float4*>(sX)[t] = reinterpret_cast<const float4*>(g_cgT + ba * 64)[t];
        const float4* r4 = reinterpret_cast<const float4*>(g_r + (size_t)ba * 4096);
        float4* x4 = reinterpret_cast<float4*>(sX + 64);
#pragma unroll
        for (int k = 0; k < 8; ++k) x4[t + k * 128] = r4[t + k * 128];
    }
    {
        const float4* w4 = reinterpret_cast<const float4*>(g_wt + w1off);
        float4* d4 = reinterpret_cast<float4*>(sW);
        for (int idx = t; idx < CIN * 16; idx += 128) d4[idx] = w4[idx];
    }
    __syncthreads();

    const int to = (t >> 3) * 4, tu = (t & 7) * 8;
    float acc[4][8];
#pragma unroll
    for (int i = 0; i < 4; ++i) {
        float bv = b1[to + i];
#pragma unroll
        for (int j = 0; j < 8; ++j) acc[i][j] = bv;
    }
    gemm_core<CIN>(sW, sX, acc, to, tu);
#pragma unroll
    for (int i = 0; i < 4; ++i)
#pragma unroll
        for (int j = 0; j < 8; ++j) acc[i][j] = fmaxf(acc[i][j], 0.0f);
    store_sH(acc, sH, to, tu);
    __syncthreads();
    colsum_top(sH, sS, t);
    {   // load W2t while colsums complete
        const float4* w4 = reinterpret_cast<const float4*>(g_wt + w2off);
        float4* d4 = reinterpret_cast<float4*>(sW);
#pragma unroll
        for (int k = 0; k < 8; ++k) d4[t + k * 128] = w4[t + k * 128];
    }
    __syncthreads();
    post_top(sH, sS, t);
    __syncthreads();

    float acc2[4][8];
#pragma unroll
    for (int i = 0; i < 4; ++i) {
        float bv = b2[to + i];
#pragma unroll
        for (int j = 0; j < 8; ++j) acc2[i][j] = bv;
    }
    gemm_core<64>(sW, sH, acc2, to, tu);
    __syncthreads();                 // everyone done reading sH
    store_sH(acc2, sH, to, tu);      // raw (no relu for phi conv2)
    __syncthreads();
    colsum_top(sH, sS, t);
    __syncthreads();
    write_post(acc2, sS, g_msgs + (size_t)ba * 4096, to, tu);
}

// ---------------- gamma kernel ----------------------------------------------
// CIN=65: feats = cg (1ch).  CIN=128: feats = r (64ch).  agg built from msgs+sums.
template<int CIN, bool FINAL>
__global__ void __launch_bounds__(128) gamma_kernel(const float* __restrict__ b1,
                                                    const float* __restrict__ b2,
                                                    int w1off, int w2off,
                                                    const float* __restrict__ w2raw,
                                                    float* __restrict__ dout) {
    extern __shared__ float smem[];
    float* sX = smem;                  // CIN*64
    float* sW = sX + CIN * 64;         // CIN*64 (>= 4096)
    float* sH = sW + CIN * 64;         // 4096
    float* sS = sH + 4096;             // 64
    const int t = threadIdx.x;
    const int ba = blockIdx.x;
    const int b = ba >> 6;
    const float inv = 1.0f / 63.0f;
    constexpr int FEAT = CIN - 64;

    if (CIN == 65) {
        if (t < 16) reinterpret_cast<float4*>(sX)[t] = reinterpret_cast<const float4*>(g_cgT + ba * 64)[t];
    } else {
        const float4* r4 = reinterpret_cast<const float4*>(g_r + (size_t)ba * 4096);
        float4* x4 = reinterpret_cast<float4*>(sX);
#pragma unroll
        for (int k = 0; k < 8; ++k) x4[t + k * 128] = r4[t + k * 128];
    }
    {   // agg channels: (sum_a - msgs)/63
        const float4* m4 = reinterpret_cast<const float4*>(g_msgs + (size_t)ba * 4096);
        const float4* s0 = reinterpret_cast<const float4*>(g_sumsP + b * 4096);
        const float4* s1 = s0 + 131072;
        const float4* s2 = s1 + 131072;
        const float4* s3 = s2 + 131072;
        float4* x4 = reinterpret_cast<float4*>(sX + FEAT * 64);
#pragma unroll
        for (int k = 0; k < 8; ++k) {
            int idx = t + k * 128;
            float4 m = m4[idx];
            float4 a0 = s0[idx], a1 = s1[idx], a2 = s2[idx], a3 = s3[idx];
            float4 v;
            v.x = ((a0.x + a1.x + a2.x + a3.x) - m.x) * inv;
            v.y = ((a0.y + a1.y + a2.y + a3.y) - m.y) * inv;
            v.z = ((a0.z + a1.z + a2.z + a3.z) - m.z) * inv;
            v.w = ((a0.w + a1.w + a2.w + a3.w) - m.w) * inv;
            x4[idx] = v;
        }
    }
    {
        const float4* w4 = reinterpret_cast<const float4*>(g_wt + w1off);
        float4* d4 = reinterpret_cast<float4*>(sW);
        for (int idx = t; idx < CIN * 16; idx += 128) d4[idx] = w4[idx];
    }
    __syncthreads();

    const int to = (t >> 3) * 4, tu = (t & 7) * 8;
    float acc[4][8];
#pragma unroll
    for (int i = 0; i < 4; ++i) {
        float bv = b1[to + i];
#pragma unroll
        for (int j = 0; j < 8; ++j) acc[i][j] = bv;
    }
    gemm_core<CIN>(sW, sX, acc, to, tu);
#pragma unroll
    for (int i = 0; i < 4; ++i)
#pragma unroll
        for (int j = 0; j < 8; ++j) acc[i][j] = fmaxf(acc[i][j], 0.0f);
    store_sH(acc, sH, to, tu);
    __syncthreads();
    colsum_top(sH, sS, t);
    if (!FINAL) {
        const float4* w4 = reinterpret_cast<const float4*>(g_wt + w2off);
        float4* d4 = reinterpret_cast<float4*>(sW);
#pragma unroll
        for (int k = 0; k < 8; ++k) d4[t + k * 128] = w4[t + k * 128];
    }
    __syncthreads();
    post_top(sH, sS, t);
    __syncthreads();

    if (!FINAL) {
        float acc2[4][8];
#pragma unroll
        for (int i = 0; i < 4; ++i) {
            float bv = b2[to + i];
#pragma unroll
            for (int j = 0; j < 8; ++j) acc2[i][j] = bv;
        }
        gemm_core<64>(sW, sH, acc2, to, tu);
#pragma unroll
        for (int i = 0; i < 4; ++i)
#pragma unroll
            for (int j = 0; j < 8; ++j) acc2[i][j] = fmaxf(acc2[i][j], 0.0f);   // relu before post
        __syncthreads();
        store_sH(acc2, sH, to, tu);
        __syncthreads();
        colsum_top(sH, sS, t);
        __syncthreads();
        write_post(acc2, sS, g_r + (size_t)ba * 4096, to, tu);
    } else {
        // conv2 is 1x64 GEMV over P (=sH); output (B,1,U,A)
        const int u = t >> 1, half = t & 1;
        float acc2 = 0.0f;
        const int c0 = half * 32;
#pragma unroll 8
        for (int c = c0; c < c0 + 32; ++c)
            acc2 = fmaf(__ldg(w2raw + c), sH[c * 64 + u], acc2);
        acc2 += __shfl_xor_sync(0xffffffffu, acc2, 1);
        if (half == 0) {
            const int a = ba & 63;
            dout[b * 4096 + u * 64 + a] = acc2 + __ldg(b2);
        }
        (void)w2off;
    }
}

// ---------------- launch -----------------------------------------------------
extern "C" void kernel_launch(void* const* d_in, const int* in_sizes, int n_in,
                              void* d_out, int out_size) {
    (void)in_sizes; (void)n_in; (void)out_size;
    const float* cg      = (const float*)d_in[0];
    const float* phi1_W1 = (const float*)d_in[1];
    const float* phi1_b1 = (const float*)d_in[2];
    const float* phi1_W2 = (const float*)d_in[3];
    const float* phi1_b2 = (const float*)d_in[4];
    const float* phiK_W1 = (const float*)d_in[5];
    const float* phiK_b1 = (const float*)d_in[6];
    const float* phiK_W2 = (const float*)d_in[7];
    const float* phiK_b2 = (const float*)d_in[8];
    const float* g1_W1   = (const float*)d_in[9];
    const float* g1_b1   = (const float*)d_in[10];
    const float* g1_W2   = (const float*)d_in[11];
    const float* g1_b2   = (const float*)d_in[12];
    const float* gK_W1   = (const float*)d_in[13];
    const float* gK_b1   = (const float*)d_in[14];
    const float* gK_W2   = (const float*)d_in[15];
    const float* gK_b2   = (const float*)d_in[16];
    const float* g5_W1   = (const float*)d_in[17];
    const float* g5_b1   = (const float*)d_in[18];
    const float* g5_W2   = (const float*)d_in[19];
    const float* g5_b2   = (const float*)d_in[20];
    float* out = (float*)d_out;

    const int SM_PHI2 = (2 * 64 + 64 * 64 + 4096 + 64) * 4;     // 33.5 KB
    const int SM_65   = (65 * 64 + 65 * 64 + 4096 + 64) * 4;    // 49.9 KB
    const int SM_128  = (128 * 64 + 128 * 64 + 4096 + 64) * 4;  // 82.2 KB

    cudaFuncSetAttribute(phi_kernel<2>,            cudaFuncAttributeMaxDynamicSharedMemorySize, SM_PHI2);
    cudaFuncSetAttribute(phi_kernel<65>,           cudaFuncAttributeMaxDynamicSharedMemorySize, SM_65);
    cudaFuncSetAttribute(gamma_kernel<65, false>,  cudaFuncAttributeMaxDynamicSharedMemorySize, SM_65);
    cudaFuncSetAttribute(gamma_kernel<128, false>, cudaFuncAttributeMaxDynamicSharedMemorySize, SM_128);
    cudaFuncSetAttribute(gamma_kernel<128, true>,  cudaFuncAttributeMaxDynamicSharedMemorySize, SM_128);

    prep_kernel<<<19, 256>>>(phi1_W1, phi1_W2, phiK_W1, phiK_W2, g1_W1, g1_W2, gK_W1, gK_W2, g5_W1);
    cgt_kernel<<<128, 256>>>(cg);

    // iteration 0
    phi_kernel<2><<<NBA, 128, SM_PHI2>>>(phi1_b1, phi1_b2, OFF_PHI1_W1T, OFF_PHI1_W2T);
    asum_kernel<<<512, 256>>>();
    gamma_kernel<65, false><<<NBA, 128, SM_65>>>(g1_b1, g1_b2, OFF_G1_W1T, OFF_G1_W2T, nullptr, nullptr);

    // iterations 1..4
    for (int i = 0; i < 4; ++i) {
        phi_kernel<65><<<NBA, 128, SM_65>>>(phiK_b1 + i * 64, phiK_b2 + i * 64,
                                            OFF_PHIK_W1T + i * 4160, OFF_PHIK_W2T + i * 4096);
        asum_kernel<<<512, 256>>>();
        if (i < 3) {
            gamma_kernel<128, false><<<NBA, 128, SM_128>>>(gK_b1 + i * 64, gK_b2 + i * 64,
                                                           OFF_GK_W1T + i * 8192, OFF_GK_W2T + i * 4096,
                                                           nullptr, nullptr);
        } else {
            gamma_kernel<128, true><<<NBA, 128, SM_128>>>(g5_b1, g5_b2,
                                                          OFF_G5_W1T, 0, g5_W2, out);
        }
    }
}

// round 2
// speedup vs baseline: 1.5150x; 1.5150x over previous
#include <cuda_runtime.h>

// Problem constants: B=128, U=64, A=64, FIN=1, FPHI=FGAM=32, PHI_OUT=GAM_OUT=64
// Intermediate layout: [b][a][c][u]  (per-(b,a) slices contiguous 64x64)

#define NBA 8192

// ---------------- scratch (device globals: allocation-free) ----------------
__device__ float g_cgT[128 * 64 * 64];                  // [b][a][u]
__device__ float g_msgs[(size_t)128 * 64 * 64 * 64];    // [b][a][c][u]
__device__ float g_r[(size_t)128 * 64 * 64 * 64];       // [b][a][c][u]
__device__ float g_sumsP[4 * 128 * 64 * 64];            // [q][b][c][u] partial a-sums
__device__ float g_wt[90560];                           // transposed weights Wt[c][o]

#define OFF_PHI1_W1T 0
#define OFF_PHI1_W2T 128
#define OFF_PHIK_W1T 4224
#define OFF_PHIK_W2T 20864
#define OFF_G1_W1T   37248
#define OFF_G1_W2T   41408
#define OFF_GK_W1T   45504
#define OFF_GK_W2T   70080
#define OFF_G5_W1T   82368

// ---------------- prep: transpose all weight matrices to Wt[c][o] ----------
__global__ void prep_kernel(const float* __restrict__ phi1W1, const float* __restrict__ phi1W2,
                            const float* __restrict__ phiKW1, const float* __restrict__ phiKW2,
                            const float* __restrict__ g1W1,   const float* __restrict__ g1W2,
                            const float* __restrict__ gKW1,   const float* __restrict__ gKW2,
                            const float* __restrict__ g5W1) {
    const int id = blockIdx.x;
    const float* src; float* dst; int C;
    if (id == 0)       { src = phi1W1;                 dst = g_wt + OFF_PHI1_W1T;              C = 2;   }
    else if (id == 1)  { src = phi1W2;                 dst = g_wt + OFF_PHI1_W2T;              C = 64;  }
    else if (id < 6)   { int i = id - 2;  src = phiKW1 + i * 4160; dst = g_wt + OFF_PHIK_W1T + i * 4160; C = 65;  }
    else if (id < 10)  { int i = id - 6;  src = phiKW2 + i * 4096; dst = g_wt + OFF_PHIK_W2T + i * 4096; C = 64;  }
    else if (id == 10) { src = g1W1;                   dst = g_wt + OFF_G1_W1T;                C = 65;  }
    else if (id == 11) { src = g1W2;                   dst = g_wt + OFF_G1_W2T;                C = 64;  }
    else if (id < 15)  { int i = id - 12; src = gKW1 + i * 8192;  dst = g_wt + OFF_GK_W1T + i * 8192;   C = 128; }
    else if (id < 18)  { int i = id - 15; src = gKW2 + i * 4096;  dst = g_wt + OFF_GK_W2T + i * 4096;   C = 64;  }
    else               { src = g5W1;                   dst = g_wt + OFF_G5_W1T;                C = 128; }
    const int n = 64 * C;
    for (int j = threadIdx.x; j < n; j += blockDim.x) {
        int c = j >> 6, o = j & 63;
        dst[j] = src[o * C + c];
    }
}

// ---------------- cg transpose: (B,U,A) -> (B,A,U) --------------------------
__global__ void cgt_kernel(const float* __restrict__ cg) {
    const int b = blockIdx.x;
    for (int j = threadIdx.x; j < 4096; j += 256) {
        int a = j >> 6, u = j & 63;
        g_cgT[b * 4096 + j] = cg[b * 4096 + u * 64 + a];
    }
}

// ---------------- partial sum over a-axis of msgs ---------------------------
__global__ void asum_kernel() {
    const int b = blockIdx.x >> 2, q = blockIdx.x & 3;
    const int t = threadIdx.x;   // 256
    float4 acc[4];
#pragma unroll
    for (int k = 0; k < 4; ++k) acc[k] = make_float4(0.f, 0.f, 0.f, 0.f);
    const float4* base = reinterpret_cast<const float4*>(g_msgs + (size_t)b * 262144 + (size_t)q * 16 * 4096);
    for (int a = 0; a < 16; ++a) {
        const float4* p = base + a * 1024;
#pragma unroll
        for (int k = 0; k < 4; ++k) {
            float4 v = p[t + k * 256];
            acc[k].x += v.x; acc[k].y += v.y; acc[k].z += v.z; acc[k].w += v.w;
        }
    }
    float4* s4 = reinterpret_cast<float4*>(g_sumsP + (size_t)q * 524288 + b * 4096);
#pragma unroll
    for (int k = 0; k < 4; ++k) s4[t + k * 256] = acc[k];
}

// ---------------- GEMM core --------------------------------------------------
// thread t: g = t>>4 owns output rows g*8..g*8+7; sub = t&15 owns u = sub*4..+3
// sX rows conflict-free (16 contiguous float4 per phase group), sW pure broadcast.
template<int CIN>
__device__ __forceinline__ void gemm_core(const float4* __restrict__ sW4, const float4* __restrict__ sX4,
                                          float acc[8][4], int g2, int sub) {
#pragma unroll 4
    for (int c = 0; c < CIN; ++c) {
        float4 x  = sX4[c * 16 + sub];
        float4 w0 = sW4[c * 16 + g2];
        float4 w1 = sW4[c * 16 + g2 + 1];
        float wv[8] = {w0.x, w0.y, w0.z, w0.w, w1.x, w1.y, w1.z, w1.w};
        float xv[4] = {x.x, x.y, x.z, x.w};
#pragma unroll
        for (int i = 0; i < 8; ++i)
#pragma unroll
            for (int j = 0; j < 4; ++j)
                acc[i][j] = fmaf(wv[i], xv[j], acc[i][j]);
    }
}

__device__ __forceinline__ void relu_acc(float acc[8][4]) {
#pragma unroll
    for (int i = 0; i < 8; ++i)
#pragma unroll
        for (int j = 0; j < 4; ++j) acc[i][j] = fmaxf(acc[i][j], 0.0f);
}

// in-register column sum over u (reduce over the 16 lanes sharing a row group)
__device__ __forceinline__ void colsum8(const float acc[8][4], float S[8]) {
#pragma unroll
    for (int i = 0; i < 8; ++i) {
        float s = (acc[i][0] + acc[i][1]) + (acc[i][2] + acc[i][3]);
        s += __shfl_xor_sync(0xffffffffu, s, 1);
        s += __shfl_xor_sync(0xffffffffu, s, 2);
        s += __shfl_xor_sync(0xffffffffu, s, 4);
        s += __shfl_xor_sync(0xffffffffu, s, 8);
        S[i] = s;
    }
}

// store with post_users transform: rows >= 32 (g>=4): x <- (S - x)/63
__device__ __forceinline__ void store_post(const float acc[8][4], const float S[8],
                                           float* __restrict__ dst, int g, int sub) {
    const float inv = 1.0f / 63.0f;
#pragma unroll
    for (int i = 0; i < 8; ++i) {
        float4 v;
        if (g >= 4) {
            v.x = (S[i] - acc[i][0]) * inv; v.y = (S[i] - acc[i][1]) * inv;
            v.z = (S[i] - acc[i][2]) * inv; v.w = (S[i] - acc[i][3]) * inv;
        } else {
            v.x = acc[i][0]; v.y = acc[i][1]; v.z = acc[i][2]; v.w = acc[i][3];
        }
        *reinterpret_cast<float4*>(dst + (g * 8 + i) * 64 + sub * 4) = v;
    }
}

// ---------------- phi kernel -------------------------------------------------
template<int CIN>
__global__ void __launch_bounds__(128) phi_kernel(const float* __restrict__ b1,
                                                  const float* __restrict__ b2,
                                                  int w1off, int w2off) {
    extern __shared__ float smem[];
    float* sX  = smem;                 // CIN*64
    float* sW1 = sX + CIN * 64;        // CIN*64
    float* sW2 = sW1 + CIN * 64;       // 4096
    float* sH  = sW2 + 4096;           // 4096
    const int t = threadIdx.x;
    const int ba = blockIdx.x;
    const int g = t >> 4, sub = t & 15, g2 = g * 2;

    if (CIN == 2) {
        if (t < 64) { float v = g_cgT[ba * 64 + t]; sX[t] = v; sX[64 + t] = v; }
    } else {
        if (t < 16) reinterpret_cast<float4*>(sX)[t] = reinterpret_cast<const float4*>(g_cgT + ba * 64)[t];
        const float4* r4 = reinterpret_cast<const float4*>(g_r + (size_t)ba * 4096);
        float4* x4 = reinterpret_cast<float4*>(sX + 64);
#pragma unroll
        for (int k = 0; k < 8; ++k) x4[t + k * 128] = r4[t + k * 128];
    }
    {
        const float4* w4 = reinterpret_cast<const float4*>(g_wt + w1off);
        float4* d4 = reinterpret_cast<float4*>(sW1);
        for (int idx = t; idx < CIN * 16; idx += 128) d4[idx] = w4[idx];
        const float4* v4 = reinterpret_cast<const float4*>(g_wt + w2off);
        float4* e4 = reinterpret_cast<float4*>(sW2);
#pragma unroll
        for (int k = 0; k < 8; ++k) e4[t + k * 128] = v4[t + k * 128];
    }
    __syncthreads();

    float acc[8][4];
#pragma unroll
    for (int i = 0; i < 8; ++i) {
        float bv = __ldg(b1 + g * 8 + i);
#pragma unroll
        for (int j = 0; j < 4; ++j) acc[i][j] = bv;
    }
    gemm_core<CIN>(reinterpret_cast<const float4*>(sW1), reinterpret_cast<const float4*>(sX), acc, g2, sub);
    relu_acc(acc);
    float S[8];
    colsum8(acc, S);
    store_post(acc, S, sH, g, sub);
    __syncthreads();

    float acc2[8][4];
#pragma unroll
    for (int i = 0; i < 8; ++i) {
        float bv = __ldg(b2 + g * 8 + i);
#pragma unroll
        for (int j = 0; j < 4; ++j) acc2[i][j] = bv;
    }
    gemm_core<64>(reinterpret_cast<const float4*>(sW2), reinterpret_cast<const float4*>(sH), acc2, g2, sub);
    float S2[8];
    colsum8(acc2, S2);                 // no relu for phi conv2
    store_post(acc2, S2, g_msgs + (size_t)ba * 4096, g, sub);
}

// ---------------- gamma kernel -----------------------------------------------
template<int CIN, bool FINAL>
__global__ void __launch_bounds__(128) gamma_kernel(const float* __restrict__ b1,
                                                    const float* __restrict__ b2,
                                                    int w1off, int w2off,
                                                    const float* __restrict__ w2raw,
                                                    float* __restrict__ dout) {
    extern __shared__ float smem[];
    float* sX  = smem;                 // CIN*64
    float* sW1 = sX + CIN * 64;        // CIN*64
    float* sW2 = sW1 + CIN * 64;       // 4096
    float* sH  = sW2 + 4096;           // 4096
    const int t = threadIdx.x;
    const int ba = blockIdx.x;
    const int b = ba >> 6;
    const int g = t >> 4, sub = t & 15, g2 = g * 2;
    const float inv = 1.0f / 63.0f;
    constexpr int FEAT = CIN - 64;

    if (CIN == 65) {
        if (t < 16) reinterpret_cast<float4*>(sX)[t] = reinterpret_cast<const float4*>(g_cgT + ba * 64)[t];
    } else {
        const float4* r4 = reinterpret_cast<const float4*>(g_r + (size_t)ba * 4096);
        float4* x4 = reinterpret_cast<float4*>(sX);
#pragma unroll
        for (int k = 0; k < 8; ++k) x4[t + k * 128] = r4[t + k * 128];
    }
    {   // agg channels: (sum_a - msgs)/63
        const float4* m4 = reinterpret_cast<const float4*>(g_msgs + (size_t)ba * 4096);
        const float4* s0 = reinterpret_cast<const float4*>(g_sumsP + b * 4096);
        const float4* s1 = s0 + 131072;
        const float4* s2 = s1 + 131072;
        const float4* s3 = s2 + 131072;
        float4* x4 = reinterpret_cast<float4*>(sX + FEAT * 64);
#pragma unroll
        for (int k = 0; k < 8; ++k) {
            int idx = t + k * 128;
            float4 m = m4[idx];
            float4 a0 = s0[idx], a1 = s1[idx], a2 = s2[idx], a3 = s3[idx];
            float4 v;
            v.x = ((a0.x + a1.x) + (a2.x + a3.x) - m.x) * inv;
            v.y = ((a0.y + a1.y) + (a2.y + a3.y) - m.y) * inv;
            v.z = ((a0.z + a1.z) + (a2.z + a3.z) - m.z) * inv;
            v.w = ((a0.w + a1.w) + (a2.w + a3.w) - m.w) * inv;
            x4[idx] = v;
        }
    }
    {
        const float4* w4 = reinterpret_cast<const float4*>(g_wt + w1off);
        float4* d4 = reinterpret_cast<float4*>(sW1);
        for (int idx = t; idx < CIN * 16; idx += 128) d4[idx] = w4[idx];
        if (!FINAL) {
            const float4* v4 = reinterpret_cast<const float4*>(g_wt + w2off);
            float4* e4 = reinterpret_cast<float4*>(sW2);
#pragma unroll
            for (int k = 0; k < 8; ++k) e4[t + k * 128] = v4[t + k * 128];
        }
    }
    __syncthreads();

    float acc[8][4];
#pragma unroll
    for (int i = 0; i < 8; ++i) {
        float bv = __ldg(b1 + g * 8 + i);
#pragma unroll
        for (int j = 0; j < 4; ++j) acc[i][j] = bv;
    }
    gemm_core<CIN>(reinterpret_cast<const float4*>(sW1), reinterpret_cast<const float4*>(sX), acc, g2, sub);
    relu_acc(acc);
    float S[8];
    colsum8(acc, S);
    store_post(acc, S, sH, g, sub);
    __syncthreads();

    if (!FINAL) {
        float acc2[8][4];
#pragma unroll
        for (int i = 0; i < 8; ++i) {
            float bv = __ldg(b2 + g * 8 + i);
#pragma unroll
            for (int j = 0; j < 4; ++j) acc2[i][j] = bv;
        }
        gemm_core<64>(reinterpret_cast<const float4*>(sW2), reinterpret_cast<const float4*>(sH), acc2, g2, sub);
        relu_acc(acc2);                 // relu BEFORE post_users
        float S2[8];
        colsum8(acc2, S2);
        store_post(acc2, S2, g_r + (size_t)ba * 4096, g, sub);
    } else {
        // conv2: 1x64 GEMV over sH; output (B,1,U,A)
        const int u = t >> 1, half = t & 1;
        float acc2 = 0.0f;
        const int c0 = half * 32;
#pragma unroll 8
        for (int c = c0; c < c0 + 32; ++c)
            acc2 = fmaf(__ldg(w2raw + c), sH[c * 64 + u], acc2);
        acc2 += __shfl_xor_sync(0xffffffffu, acc2, 1);
        if (half == 0) {
            const int a = ba & 63;
            dout[b * 4096 + u * 64 + a] = acc2 + __ldg(b2);
        }
        (void)w2off;
    }
}

// ---------------- launch -----------------------------------------------------
extern "C" void kernel_launch(void* const* d_in, const int* in_sizes, int n_in,
                              void* d_out, int out_size) {
    (void)in_sizes; (void)n_in; (void)out_size;
    const float* cg      = (const float*)d_in[0];
    const float* phi1_W1 = (const float*)d_in[1];
    const float* phi1_b1 = (const float*)d_in[2];
    const float* phi1_W2 = (const float*)d_in[3];
    const float* phi1_b2 = (const float*)d_in[4];
    const float* phiK_W1 = (const float*)d_in[5];
    const float* phiK_b1 = (const float*)d_in[6];
    const float* phiK_W2 = (const float*)d_in[7];
    const float* phiK_b2 = (const float*)d_in[8];
    const float* g1_W1   = (const float*)d_in[9];
    const float* g1_b1   = (const float*)d_in[10];
    const float* g1_W2   = (const float*)d_in[11];
    const float* g1_b2   = (const float*)d_in[12];
    const float* gK_W1   = (const float*)d_in[13];
    const float* gK_b1   = (const float*)d_in[14];
    const float* gK_W2   = (const float*)d_in[15];
    const float* gK_b2   = (const float*)d_in[16];
    const float* g5_W1   = (const float*)d_in[17];
    const float* g5_b1   = (const float*)d_in[18];
    const float* g5_W2   = (const float*)d_in[19];
    const float* g5_b2   = (const float*)d_in[20];
    float* out = (float*)d_out;

    const int SM_PHI2 = (2 * 64 * 2 + 4096 + 4096) * 4;
    const int SM_65   = (65 * 64 * 2 + 4096 + 4096) * 4;
    const int SM_128  = (128 * 64 * 2 + 4096 + 4096) * 4;

    cudaFuncSetAttribute(phi_kernel<2>,            cudaFuncAttributeMaxDynamicSharedMemorySize, SM_PHI2);
    cudaFuncSetAttribute(phi_kernel<65>,           cudaFuncAttributeMaxDynamicSharedMemorySize, SM_65);
    cudaFuncSetAttribute(gamma_kernel<65, false>,  cudaFuncAttributeMaxDynamicSharedMemorySize, SM_65);
    cudaFuncSetAttribute(gamma_kernel<128, false>, cudaFuncAttributeMaxDynamicSharedMemorySize, SM_128);
    cudaFuncSetAttribute(gamma_kernel<128, true>,  cudaFuncAttributeMaxDynamicSharedMemorySize, SM_128);

    prep_kernel<<<19, 256>>>(phi1_W1, phi1_W2, phiK_W1, phiK_W2, g1_W1, g1_W2, gK_W1, gK_W2, g5_W1);
    cgt_kernel<<<128, 256>>>(cg);

    // iteration 0
    phi_kernel<2><<<NBA, 128, SM_PHI2>>>(phi1_b1, phi1_b2, OFF_PHI1_W1T, OFF_PHI1_W2T);
    asum_kernel<<<512, 256>>>();
    gamma_kernel<65, false><<<NBA, 128, SM_65>>>(g1_b1, g1_b2, OFF_G1_W1T, OFF_G1_W2T, nullptr, nullptr);

    // iterations 1..4
    for (int i = 0; i < 4; ++i) {
        phi_kernel<65><<<NBA, 128, SM_65>>>(phiK_b1 + i * 64, phiK_b2 + i * 64,
                                            OFF_PHIK_W1T + i * 4160, OFF_PHIK_W2T + i * 4096);
        asum_kernel<<<512, 256>>>();
        if (i < 3) {
            gamma_kernel<128, false><<<NBA, 128, SM_128>>>(gK_b1 + i * 64, gK_b2 + i * 64,
                                                           OFF_GK_W1T + i * 8192, OFF_GK_W2T + i * 4096,
                                                           nullptr, nullptr);
        } else {
            gamma_kernel<128, true><<<NBA, 128, SM_128>>>(g5_b1, g5_b2,
                                                          OFF_G5_W1T, 0, g5_W2, out);
        }
    }
}

// round 3
// speedup vs baseline: 2.3234x; 1.5335x over previous
#include <cuda_runtime.h>

// Problem constants: B=128, U=64, A=64, FIN=1, FPHI=FGAM=32, PHI_OUT=GAM_OUT=64
// Intermediate layout: [b][a][c][u]  (per-(b,a) slices contiguous 64x64)

#define NBA 8192

// ---------------- scratch (device globals: allocation-free) ----------------
__device__ float g_cgT[128 * 64 * 64];                  // [b][a][u]
__device__ float g_msgs[(size_t)128 * 64 * 64 * 64];    // [b][a][c][u]
__device__ float g_r[(size_t)128 * 64 * 64 * 64];       // [b][a][c][u]
__device__ float g_sumsP[4 * 128 * 64 * 64];            // [q][b][c][u] partial a-sums
__device__ float g_wt[90560];                           // transposed weights Wt[c][o]

#define OFF_PHI1_W1T 0
#define OFF_PHI1_W2T 128
#define OFF_PHIK_W1T 4224
#define OFF_PHIK_W2T 20864
#define OFF_G1_W1T   37248
#define OFF_G1_W2T   41408
#define OFF_GK_W1T   45504
#define OFF_GK_W2T   70080
#define OFF_G5_W1T   82368

// ---------------- prep: transpose all weight matrices to Wt[c][o] ----------
__global__ void prep_kernel(const float* __restrict__ phi1W1, const float* __restrict__ phi1W2,
                            const float* __restrict__ phiKW1, const float* __restrict__ phiKW2,
                            const float* __restrict__ g1W1,   const float* __restrict__ g1W2,
                            const float* __restrict__ gKW1,   const float* __restrict__ gKW2,
                            const float* __restrict__ g5W1) {
    const int id = blockIdx.x;
    const float* src; float* dst; int C;
    if (id == 0)       { src = phi1W1;                 dst = g_wt + OFF_PHI1_W1T;              C = 2;   }
    else if (id == 1)  { src = phi1W2;                 dst = g_wt + OFF_PHI1_W2T;              C = 64;  }
    else if (id < 6)   { int i = id - 2;  src = phiKW1 + i * 4160; dst = g_wt + OFF_PHIK_W1T + i * 4160; C = 65;  }
    else if (id < 10)  { int i = id - 6;  src = phiKW2 + i * 4096; dst = g_wt + OFF_PHIK_W2T + i * 4096; C = 64;  }
    else if (id == 10) { src = g1W1;                   dst = g_wt + OFF_G1_W1T;                C = 65;  }
    else if (id == 11) { src = g1W2;                   dst = g_wt + OFF_G1_W2T;                C = 64;  }
    else if (id < 15)  { int i = id - 12; src = gKW1 + i * 8192;  dst = g_wt + OFF_GK_W1T + i * 8192;   C = 128; }
    else if (id < 18)  { int i = id - 15; src = gKW2 + i * 4096;  dst = g_wt + OFF_GK_W2T + i * 4096;   C = 64;  }
    else               { src = g5W1;                   dst = g_wt + OFF_G5_W1T;                C = 128; }
    const int n = 64 * C;
    for (int j = threadIdx.x; j < n; j += blockDim.x) {
        int c = j >> 6, o = j & 63;
        dst[j] = src[o * C + c];
    }
}

// ---------------- cg transpose: (B,U,A) -> (B,A,U) --------------------------
__global__ void cgt_kernel(const float* __restrict__ cg) {
    const int b = blockIdx.x;
    for (int j = threadIdx.x; j < 4096; j += 256) {
        int a = j >> 6, u = j & 63;
        g_cgT[b * 4096 + j] = cg[b * 4096 + u * 64 + a];
    }
}

// ---------------- partial sum over a-axis of msgs ---------------------------
__global__ void asum_kernel() {
    const int b = blockIdx.x >> 2, q = blockIdx.x & 3;
    const int t = threadIdx.x;   // 256
    float4 acc[4];
#pragma unroll
    for (int k = 0; k < 4; ++k) acc[k] = make_float4(0.f, 0.f, 0.f, 0.f);
    const float4* base = reinterpret_cast<const float4*>(g_msgs + (size_t)b * 262144 + (size_t)q * 16 * 4096);
    for (int a = 0; a < 16; ++a) {
        const float4* p = base + a * 1024;
#pragma unroll
        for (int k = 0; k < 4; ++k) {
            float4 v = p[t + k * 256];
            acc[k].x += v.x; acc[k].y += v.y; acc[k].z += v.z; acc[k].w += v.w;
        }
    }
    float4* s4 = reinterpret_cast<float4*>(g_sumsP + (size_t)q * 524288 + b * 4096);
#pragma unroll
    for (int k = 0; k < 4; ++k) s4[t + k * 256] = acc[k];
}

// ---------------- GEMM core --------------------------------------------------
// thread t: g = t>>4 owns output rows g*8..g*8+7; sub = t&15 owns u = sub*4..+3
// sX rows conflict-free (16 contiguous float4 per phase group), sW pure broadcast.
template<int CIN>
__device__ __forceinline__ void gemm_core(const float4* __restrict__ sW4, const float4* __restrict__ sX4,
                                          float acc[8][4], int g2, int sub) {
#pragma unroll 4
    for (int c = 0; c < CIN; ++c) {
        float4 x  = sX4[c * 16 + sub];
        float4 w0 = sW4[c * 16 + g2];
        float4 w1 = sW4[c * 16 + g2 + 1];
        float wv[8] = {w0.x, w0.y, w0.z, w0.w, w1.x, w1.y, w1.z, w1.w};
        float xv[4] = {x.x, x.y, x.z, x.w};
#pragma unroll
        for (int i = 0; i < 8; ++i)
#pragma unroll
            for (int j = 0; j < 4; ++j)
                acc[i][j] = fmaf(wv[i], xv[j], acc[i][j]);
    }
}

__device__ __forceinline__ void relu_acc(float acc[8][4]) {
#pragma unroll
    for (int i = 0; i < 8; ++i)
#pragma unroll
        for (int j = 0; j < 4; ++j) acc[i][j] = fmaxf(acc[i][j], 0.0f);
}

// in-register column sum over u (reduce over the 16 lanes sharing a row group)
__device__ __forceinline__ void colsum8(const float acc[8][4], float S[8]) {
#pragma unroll
    for (int i = 0; i < 8; ++i) {
        float s = (acc[i][0] + acc[i][1]) + (acc[i][2] + acc[i][3]);
        s += __shfl_xor_sync(0xffffffffu, s, 1);
        s += __shfl_xor_sync(0xffffffffu, s, 2);
        s += __shfl_xor_sync(0xffffffffu, s, 4);
        s += __shfl_xor_sync(0xffffffffu, s, 8);
        S[i] = s;
    }
}

// store with post_users transform: rows >= 32 (g>=4): x <- (S - x)/63
__device__ __forceinline__ void store_post(const float acc[8][4], const float S[8],
                                           float* __restrict__ dst, int g, int sub) {
    const float inv = 1.0f / 63.0f;
#pragma unroll
    for (int i = 0; i < 8; ++i) {
        float4 v;
        if (g >= 4) {
            v.x = (S[i] - acc[i][0]) * inv; v.y = (S[i] - acc[i][1]) * inv;
            v.z = (S[i] - acc[i][2]) * inv; v.w = (S[i] - acc[i][3]) * inv;
        } else {
            v.x = acc[i][0]; v.y = acc[i][1]; v.z = acc[i][2]; v.w = acc[i][3];
        }
        *reinterpret_cast<float4*>(dst + (g * 8 + i) * 64 + sub * 4) = v;
    }
}

// ---------------- phi kernel -------------------------------------------------
template<int CIN>
__global__ void __launch_bounds__(128) phi_kernel(const float* __restrict__ b1,
                                                  const float* __restrict__ b2,
                                                  int w1off, int w2off) {
    extern __shared__ float smem[];
    float* sX  = smem;                 // CIN*64
    float* sW1 = sX + CIN * 64;        // CIN*64
    float* sW2 = sW1 + CIN * 64;       // 4096
    float* sH  = sW2 + 4096;           // 4096
    const int t = threadIdx.x;
    const int ba = blockIdx.x;
    const int g = t >> 4, sub = t & 15, g2 = g * 2;

    if (CIN == 2) {
        if (t < 64) { float v = g_cgT[ba * 64 + t]; sX[t] = v; sX[64 + t] = v; }
    } else {
        if (t < 16) reinterpret_cast<float4*>(sX)[t] = reinterpret_cast<const float4*>(g_cgT + ba * 64)[t];
        const float4* r4 = reinterpret_cast<const float4*>(g_r + (size_t)ba * 4096);
        float4* x4 = reinterpret_cast<float4*>(sX + 64);
#pragma unroll
        for (int k = 0; k < 8; ++k) x4[t + k * 128] = r4[t + k * 128];
    }
    {
        const float4* w4 = reinterpret_cast<const float4*>(g_wt + w1off);
        float4* d4 = reinterpret_cast<float4*>(sW1);
        for (int idx = t; idx < CIN * 16; idx += 128) d4[idx] = w4[idx];
        const float4* v4 = reinterpret_cast<const float4*>(g_wt + w2off);
        float4* e4 = reinterpret_cast<float4*>(sW2);
#pragma unroll
        for (int k = 0; k < 8; ++k) e4[t + k * 128] = v4[t + k * 128];
    }
    __syncthreads();

    float acc[8][4];
#pragma unroll
    for (int i = 0; i < 8; ++i) {
        float bv = __ldg(b1 + g * 8 + i);
#pragma unroll
        for (int j = 0; j < 4; ++j) acc[i][j] = bv;
    }
    gemm_core<CIN>(reinterpret_cast<const float4*>(sW1), reinterpret_cast<const float4*>(sX), acc, g2, sub);
    relu_acc(acc);
    float S[8];
    colsum8(acc, S);
    store_post(acc, S, sH, g, sub);
    __syncthreads();

    float acc2[8][4];
#pragma unroll
    for (int i = 0; i < 8; ++i) {
        float bv = __ldg(b2 + g * 8 + i);
#pragma unroll
        for (int j = 0; j < 4; ++j) acc2[i][j] = bv;
    }
    gemm_core<64>(reinterpret_cast<const float4*>(sW2), reinterpret_cast<const float4*>(sH), acc2, g2, sub);
    float S2[8];
    colsum8(acc2, S2);                 // no relu for phi conv2
    store_post(acc2, S2, g_msgs + (size_t)ba * 4096, g, sub);
}

// ---------------- gamma kernel -----------------------------------------------
template<int CIN, bool FINAL>
__global__ void __launch_bounds__(128) gamma_kernel(const float* __restrict__ b1,
                                                    const float* __restrict__ b2,
                                                    int w1off, int w2off,
                                                    const float* __restrict__ w2raw,
                                                    float* __restrict__ dout) {
    extern __shared__ float smem[];
    float* sX  = smem;                 // CIN*64
    float* sW1 = sX + CIN * 64;        // CIN*64
    float* sW2 = sW1 + CIN * 64;       // 4096
    float* sH  = sW2 + 4096;           // 4096
    const int t = threadIdx.x;
    const int ba = blockIdx.x;
    const int b = ba >> 6;
    const int g = t >> 4, sub = t & 15, g2 = g * 2;
    const float inv = 1.0f / 63.0f;
    constexpr int FEAT = CIN - 64;

    if (CIN == 65) {
        if (t < 16) reinterpret_cast<float4*>(sX)[t] = reinterpret_cast<const float4*>(g_cgT + ba * 64)[t];
    } else {
        const float4* r4 = reinterpret_cast<const float4*>(g_r + (size_t)ba * 4096);
        float4* x4 = reinterpret_cast<float4*>(sX);
#pragma unroll
        for (int k = 0; k < 8; ++k) x4[t + k * 128] = r4[t + k * 128];
    }
    {   // agg channels: (sum_a - msgs)/63
        const float4* m4 = reinterpret_cast<const float4*>(g_msgs + (size_t)ba * 4096);
        const float4* s0 = reinterpret_cast<const float4*>(g_sumsP + b * 4096);
        const float4* s1 = s0 + 131072;
        const float4* s2 = s1 + 131072;
        const float4* s3 = s2 + 131072;
        float4* x4 = reinterpret_cast<float4*>(sX + FEAT * 64);
#pragma unroll
        for (int k = 0; k < 8; ++k) {
            int idx = t + k * 128;
            float4 m = m4[idx];
            float4 a0 = s0[idx], a1 = s1[idx], a2 = s2[idx], a3 = s3[idx];
            float4 v;
            v.x = ((a0.x + a1.x) + (a2.x + a3.x) - m.x) * inv;
            v.y = ((a0.y + a1.y) + (a2.y + a3.y) - m.y) * inv;
            v.z = ((a0.z + a1.z) + (a2.z + a3.z) - m.z) * inv;
            v.w = ((a0.w + a1.w) + (a2.w + a3.w) - m.w) * inv;
            x4[idx] = v;
        }
    }
    {
        const float4* w4 = reinterpret_cast<const float4*>(g_wt + w1off);
        float4* d4 = reinterpret_cast<float4*>(sW1);
        for (int idx = t; idx < CIN * 16; idx += 128) d4[idx] = w4[idx];
        if (!FINAL) {
            const float4* v4 = reinterpret_cast<const float4*>(g_wt + w2off);
            float4* e4 = reinterpret_cast<float4*>(sW2);
#pragma unroll
            for (int k = 0; k < 8; ++k) e4[t + k * 128] = v4[t + k * 128];
        }
    }
    __syncthreads();

    float acc[8][4];
#pragma unroll
    for (int i = 0; i < 8; ++i) {
        float bv = __ldg(b1 + g * 8 + i);
#pragma unroll
        for (int j = 0; j < 4; ++j) acc[i][j] = bv;
    }
    gemm_core<CIN>(reinterpret_cast<const float4*>(sW1), reinterpret_cast<const float4*>(sX), acc, g2, sub);
    relu_acc(acc);
    float S[8];
    colsum8(acc, S);
    store_post(acc, S, sH, g, sub);
    __syncthreads();

    if (!FINAL) {
        float acc2[8][4];
#pragma unroll
        for (int i = 0; i < 8; ++i) {
            float bv = __ldg(b2 + g * 8 + i);
#pragma unroll
            for (int j = 0; j < 4; ++j) acc2[i][j] = bv;
        }
        gemm_core<64>(reinterpret_cast<const float4*>(sW2), reinterpret_cast<const float4*>(sH), acc2, g2, sub);
        relu_acc(acc2);                 // relu BEFORE post_users
        float S2[8];
        colsum8(acc2, S2);
        store_post(acc2, S2, g_r + (size_t)ba * 4096, g, sub);
    } else {
        // conv2: 1x64 GEMV over sH; output (B,1,U,A)
        const int u = t >> 1, half = t & 1;
        float acc2 = 0.0f;
        const int c0 = half * 32;
#pragma unroll 8
        for (int c = c0; c < c0 + 32; ++c)
            acc2 = fmaf(__ldg(w2raw + c), sH[c * 64 + u], acc2);
        acc2 += __shfl_xor_sync(0xffffffffu, acc2, 1);
        if (half == 0) {
            const int a = ba & 63;
            dout[b * 4096 + u * 64 + a] = acc2 + __ldg(b2);
        }
        (void)w2off;
    }
}

// ---------------- launch -----------------------------------------------------
extern "C" void kernel_launch(void* const* d_in, const int* in_sizes, int n_in,
                              void* d_out, int out_size) {
    (void)in_sizes; (void)n_in; (void)out_size;
    const float* cg      = (const float*)d_in[0];
    const float* phi1_W1 = (const float*)d_in[1];
    const float* phi1_b1 = (const float*)d_in[2];
    const float* phi1_W2 = (const float*)d_in[3];
    const float* phi1_b2 = (const float*)d_in[4];
    const float* phiK_W1 = (const float*)d_in[5];
    const float* phiK_b1 = (const float*)d_in[6];
    const float* phiK_W2 = (const float*)d_in[7];
    const float* phiK_b2 = (const float*)d_in[8];
    const float* g1_W1   = (const float*)d_in[9];
    const float* g1_b1   = (const float*)d_in[10];
    const float* g1_W2   = (const float*)d_in[11];
    const float* g1_b2   = (const float*)d_in[12];
    const float* gK_W1   = (const float*)d_in[13];
    const float* gK_b1   = (const float*)d_in[14];
    const float* gK_W2   = (const float*)d_in[15];
    const float* gK_b2   = (const float*)d_in[16];
    const float* g5_W1   = (const float*)d_in[17];
    const float* g5_b1   = (const float*)d_in[18];
    const float* g5_W2   = (const float*)d_in[19];
    const float* g5_b2   = (const float*)d_in[20];
    float* out = (float*)d_out;

    const int SM_PHI2 = (2 * 64 * 2 + 4096 + 4096) * 4;
    const int SM_65   = (65 * 64 * 2 + 4096 + 4096) * 4;
    const int SM_128  = (128 * 64 * 2 + 4096 + 4096) * 4;

    cudaFuncSetAttribute(phi_kernel<2>,            cudaFuncAttributeMaxDynamicSharedMemorySize, SM_PHI2);
    cudaFuncSetAttribute(phi_kernel<65>,           cudaFuncAttributeMaxDynamicSharedMemorySize, SM_65);
    cudaFuncSetAttribute(gamma_kernel<65, false>,  cudaFuncAttributeMaxDynamicSharedMemorySize, SM_65);
    cudaFuncSetAttribute(gamma_kernel<128, false>, cudaFuncAttributeMaxDynamicSharedMemorySize, SM_128);
    cudaFuncSetAttribute(gamma_kernel<128, true>,  cudaFuncAttributeMaxDynamicSharedMemorySize, SM_128);

    prep_kernel<<<19, 256>>>(phi1_W1, phi1_W2, phiK_W1, phiK_W2, g1_W1, g1_W2, gK_W1, gK_W2, g5_W1);
    cgt_kernel<<<128, 256>>>(cg);

    // iteration 0
    phi_kernel<2><<<NBA, 128, SM_PHI2>>>(phi1_b1, phi1_b2, OFF_PHI1_W1T, OFF_PHI1_W2T);
    asum_kernel<<<512, 256>>>();
    gamma_kernel<65, false><<<NBA, 128, SM_65>>>(g1_b1, g1_b2, OFF_G1_W1T, OFF_G1_W2T, nullptr, nullptr);

    // iterations 1..4
    for (int i = 0; i < 4; ++i) {
        phi_kernel<65><<<NBA, 128, SM_65>>>(phiK_b1 + i * 64, phiK_b2 + i * 64,
                                            OFF_PHIK_W1T + i * 4160, OFF_PHIK_W2T + i * 4096);
        asum_kernel<<<512, 256>>>();
        if (i < 3) {
            gamma_kernel<128, false><<<NBA, 128, SM_128>>>(gK_b1 + i * 64, gK_b2 + i * 64,
                                                           OFF_GK_W1T + i * 8192, OFF_GK_W2T + i * 4096,
                                                           nullptr, nullptr);
        } else {
            gamma_kernel<128, true><<<NBA, 128, SM_128>>>(g5_b1, g5_b2,
                                                          OFF_G5_W1T, 0, g5_W2, out);
        }
    }
}